// round 15
// baseline (speedup 1.0000x reference)
#include <cuda_runtime.h>
#include <cuda_bf16.h>
#include <math.h>
#include <stdint.h>

// B=8, N=1024, C=768, H=12, D=64, level=8, thresh=1.0, scale=0.125
__device__ __align__(16) signed char g_q[8 * 12 * 1024 * 64];
__device__ __align__(16) signed char g_k[8 * 12 * 1024 * 64];
__device__ __align__(16) signed char g_v[8 * 12 * 1024 * 64];
__device__ __align__(16) signed char g_t[8192 * 768];
__device__ int g_flag[64];   // per-128-row-group: any attention spike?

// bf16 planes for the qkv GEMM inputs
__device__ __align__(16) __nv_bfloat16 g_xh[8192 * 768];
__device__ __align__(16) __nv_bfloat16 g_wh[2304 * 768];

__device__ __forceinline__ int tern_of(float v) {
    const float u = v + 0.5f;
    return (u >= 1.0f) ? 1 : ((u < 0.0f) ? -1 : 0);
}

__device__ __forceinline__ uint32_t smem_u32(const void* p) {
    uint32_t a;
    asm("{ .reg .u64 t; cvta.to.shared.u64 t, %1; cvt.u32.u64 %0, t; }" : "=r"(a) : "l"(p));
    return a;
}
__device__ __forceinline__ void ldm_x4(uint32_t& r0, uint32_t& r1, uint32_t& r2, uint32_t& r3,
                                       uint32_t addr) {
    asm volatile("ldmatrix.sync.aligned.m8n8.x4.shared.b16 {%0,%1,%2,%3}, [%4];"
                 : "=r"(r0), "=r"(r1), "=r"(r2), "=r"(r3) : "r"(addr));
}
__device__ __forceinline__ void mma_bf16(float* c, const uint32_t* a, uint32_t b0, uint32_t b1) {
    asm volatile(
        "mma.sync.aligned.m16n8k16.row.col.f32.bf16.bf16.f32 "
        "{%0,%1,%2,%3}, {%4,%5,%6,%7}, {%8,%9}, {%0,%1,%2,%3};"
        : "+f"(c[0]), "+f"(c[1]), "+f"(c[2]), "+f"(c[3])
        : "r"(a[0]), "r"(a[1]), "r"(a[2]), "r"(a[3]), "r"(b0), "r"(b1));
}
__device__ __forceinline__ void mma_s8(int* c, const uint32_t* a, uint32_t b0, uint32_t b1) {
    asm volatile(
        "mma.sync.aligned.m16n8k32.row.col.s32.s8.s8.s32 "
        "{%0,%1,%2,%3}, {%4,%5,%6,%7}, {%8,%9}, {%0,%1,%2,%3};"
        : "+r"(c[0]), "+r"(c[1]), "+r"(c[2]), "+r"(c[3])
        : "r"(a[0]), "r"(a[1]), "r"(a[2]), "r"(a[3]), "r"(b0), "r"(b1));
}

// ---------------------------------------------------------------------------
// Prepass: fp32 X, W_qkv -> bf16 (round-to-nearest). Also init flags.
// ---------------------------------------------------------------------------
__global__ void __launch_bounds__(256) split_kernel(const float* __restrict__ X,
                                                    const float* __restrict__ W) {
    const unsigned i = blockIdx.x * 256 + threadIdx.x;
    if (blockIdx.x == 0 && threadIdx.x < 64) g_flag[threadIdx.x] = 0;

    const float* src;
    __nv_bfloat16* dh;
    unsigned j;
    if (i < 1572864u) {            // X: 8192*768/4 float4s
        src = X; dh = g_xh; j = i;
    } else if (i < 2015232u) {     // W: 2304*768/4
        src = W; dh = g_wh; j = i - 1572864u;
    } else return;

    const float4 v = ((const float4*)src)[j];
    const float f[4] = {v.x, v.y, v.z, v.w};
    unsigned hw[2];
#pragma unroll
    for (int p = 0; p < 2; p++) {
        const __nv_bfloat16 h0 = __float2bfloat16(f[2 * p]);
        const __nv_bfloat16 h1 = __float2bfloat16(f[2 * p + 1]);
        hw[p] = (unsigned)__bfloat16_as_ushort(h0) | ((unsigned)__bfloat16_as_ushort(h1) << 16);
    }
    ((uint2*)dh)[j] = make_uint2(hw[0], hw[1]);
}

// ---------------------------------------------------------------------------
// GEMM1 via mma.sync bf16 (unchanged from passing R12 build).
// ---------------------------------------------------------------------------
#define RS 80
#define PLANE 10240
#define BUFB (2 * PLANE)
#define QKV_SMEM (2 * BUFB)

__global__ void __launch_bounds__(256, 2) gemm_qkv_kernel() {
    extern __shared__ char sm[];
    const uint32_t sb = smem_u32(sm);
    const int tid = threadIdx.x;
    const int wid = tid >> 5, lane = tid & 31;
    const int rowBase = blockIdx.y * 128;
    const int colBase = blockIdx.x * 128;

    const int warp_m = (wid >> 1) * 32;
    const int warp_n = (wid & 1) * 64;
    const int r0i = tid >> 2, kq = (tid & 3) * 8;

    float acc[2][8][4];
#pragma unroll
    for (int mt = 0; mt < 2; mt++)
#pragma unroll
        for (int nt = 0; nt < 8; nt++)
#pragma unroll
            for (int e = 0; e < 4; e++) acc[mt][nt][e] = 0.0f;

#pragma unroll
    for (int half = 0; half < 2; half++) {
        const int row = r0i + half * 64;
        const uint32_t so = (uint32_t)(row * RS + kq * 2);
        *(uint4*)(sm + 0 * PLANE + so) = *(const uint4*)(g_xh + (size_t)(rowBase + row) * 768 + kq);
        *(uint4*)(sm + 1 * PLANE + so) = *(const uint4*)(g_wh + (size_t)(colBase + row) * 768 + kq);
    }
    __syncthreads();

    const int j = lane >> 3, rr = lane & 7;
    const int arow = warp_m + (j & 1) * 8 + rr;
    const int brow = warp_n + (j & 1) * 8 + rr;
    const int kof = (j >> 1) * 16;

#pragma unroll 1
    for (int c = 0; c < 24; c++) {
        const int buf = c & 1;
        uint4 st[4];
        const bool nxt = c < 23;
        if (nxt) {
            const int kt = (c + 1) * 32;
#pragma unroll
            for (int half = 0; half < 2; half++) {
                const int row = r0i + half * 64;
                st[half * 2 + 0] = *(const uint4*)(g_xh + (size_t)(rowBase + row) * 768 + kt + kq);
                st[half * 2 + 1] = *(const uint4*)(g_wh + (size_t)(colBase + row) * 768 + kt + kq);
            }
        }

        const uint32_t aB = sb + buf * BUFB;
        const uint32_t bB = aB + PLANE;
#pragma unroll
        for (int ks = 0; ks < 2; ks++) {
            const uint32_t ko = ks * 32 + kof;
            uint32_t ah[2][4];
#pragma unroll
            for (int mt = 0; mt < 2; mt++) {
                const uint32_t ad = aB + (arow + mt * 16) * RS + ko;
                ldm_x4(ah[mt][0], ah[mt][1], ah[mt][2], ah[mt][3], ad);
            }
#pragma unroll
            for (int ntp = 0; ntp < 4; ntp++) {
                const uint32_t bd = bB + (brow + ntp * 16) * RS + ko;
                uint32_t bh0, bh1, bh2, bh3;
                ldm_x4(bh0, bh1, bh2, bh3, bd);
#pragma unroll
                for (int mt = 0; mt < 2; mt++) {
                    mma_bf16(acc[mt][2 * ntp],     ah[mt], bh0, bh2);
                    mma_bf16(acc[mt][2 * ntp + 1], ah[mt], bh1, bh3);
                }
            }
        }

        if (nxt) {
            char* base = sm + (buf ^ 1) * BUFB;
#pragma unroll
            for (int half = 0; half < 2; half++) {
                const int row = r0i + half * 64;
                const uint32_t so = (uint32_t)(row * RS + kq * 2);
                *(uint4*)(base + 0 * PLANE + so) = st[half * 2 + 0];
                *(uint4*)(base + 1 * PLANE + so) = st[half * 2 + 1];
            }
        }
        __syncthreads();
    }

    const int sec = colBase / 768;
    signed char* dst = (sec == 0) ? g_q : ((sec == 1) ? g_k : g_v);
    const int colSec = colBase - sec * 768;
    const int groupID = lane >> 2, tid4 = lane & 3;

#pragma unroll
    for (int mt = 0; mt < 2; mt++) {
        const int row0 = rowBase + warp_m + mt * 16 + groupID;
        const int row1 = row0 + 8;
        const int bb = row0 >> 10;
        const int nn0 = row0 & 1023, nn1 = row1 & 1023;
#pragma unroll
        for (int nt = 0; nt < 8; nt++) {
            const int gcol = colSec + warp_n + nt * 8 + tid4 * 2;
            const int h = gcol >> 6, d0 = gcol & 63;
            const float* cc = acc[mt][nt];
            char2 p0, p1;
            p0.x = (char)tern_of(cc[0]); p0.y = (char)tern_of(cc[1]);
            p1.x = (char)tern_of(cc[2]); p1.y = (char)tern_of(cc[3]);
            *(char2*)(dst + ((size_t)((bb * 12 + h) * 1024 + nn0) * 64 + d0)) = p0;
            *(char2*)(dst + ((size_t)((bb * 12 + h) * 1024 + nn1) * 64 + d0)) = p1;
        }
    }
}

// ---------------------------------------------------------------------------
// Attention via s8 IMMA. Logits are exact integers (identical to dp4a).
// Only the argmax logit can spike; spike iff 1/Z >= 0.5 (margin Z~70 vs 2,
// so Z summation order is irrelevant). exp via 129-entry table.
// CTA = (b,h) x 128 rows; 8 warps x 16 rows; two sweeps over 1024 keys
// (pass A: row max; pass B: Z + argmax), dots recomputed by IMMA.
// ---------------------------------------------------------------------------
#define AK_OFF 0          // K: [1024][80]
#define AQ_OFF 81920      // Q: [128][80]
#define AT_OFF 92160      // table: 129 floats
#define ATTN_SMEM 92800

__global__ void __launch_bounds__(256, 2) attn_kernel() {
    extern __shared__ char smc[];
    const uint32_t sb = smem_u32(smc);
    float* table = (float*)(smc + AT_OFF);

    const int bh = blockIdx.x;
    const int bb = bh / 12, h = bh % 12;
    const int tid = threadIdx.x;
    const int lane = tid & 31, wid = tid >> 5;

    const signed char* kbase = g_k + (size_t)bh * 65536;
    const signed char* vbase = g_v + (size_t)bh * 65536;
    const signed char* qbase = g_q + (size_t)bh * 65536;
    const int rowBase = blockIdx.y * 128;

    if (tid < 129) table[tid] = expf(0.125f * (float)(tid - 128));

    // stage K (1024 x 64B, stride 80) and Q (128 rows)
    for (int i = tid; i < 4096; i += 256) {
        const int key = i >> 2, seg = i & 3;
        *(int4*)(smc + AK_OFF + key * 80 + seg * 16) =
            *(const int4*)(kbase + key * 64 + seg * 16);
    }
    for (int i = tid; i < 512; i += 256) {
        const int row = i >> 2, seg = i & 3;
        *(int4*)(smc + AQ_OFF + row * 80 + seg * 16) =
            *(const int4*)(qbase + (size_t)(rowBase + row) * 64 + seg * 16);
    }
    __syncthreads();

    // A fragments for this warp's 16 rows (tile order matches mma a0..a3)
    const int t = lane >> 3;
    const uint32_t qaddr = sb + AQ_OFF +
        (uint32_t)((wid * 16 + (t & 1) * 8 + (lane & 7)) * 80 + (t >> 1) * 16);
    uint32_t a0[4], a1[4];
    ldm_x4(a0[0], a0[1], a0[2], a0[3], qaddr);        // k bytes 0-31
    ldm_x4(a1[0], a1[1], a1[2], a1[3], qaddr + 32);   // k bytes 32-63

    // B ldmatrix base: tiles = {keys0-7 B0-15, keys0-7 B16-31, keys8-15 B0-15, keys8-15 B16-31}
    const uint32_t kaddr = sb + AK_OFF +
        (uint32_t)(((t >> 1) * 8 + (lane & 7)) * 80 + (t & 1) * 16);

    // ---- pass A: row maxima ----
    int mx0 = -1000, mx1 = -1000;    // rows lane/4 and lane/4+8 (local)
#pragma unroll 4
    for (int nt = 0; nt < 64; nt++) {
        const uint32_t ka = kaddr + (uint32_t)(nt * 16 * 80);
        uint32_t b0[4], b1[4];
        ldm_x4(b0[0], b0[1], b0[2], b0[3], ka);        // bytes 0-31, 16 keys
        ldm_x4(b1[0], b1[1], b1[2], b1[3], ka + 32);   // bytes 32-63
        int c[4];
        c[0] = c[1] = c[2] = c[3] = 0;                 // keys 16nt..+7
        mma_s8(c, a0, b0[0], b0[1]);
        mma_s8(c, a1, b1[0], b1[1]);
        mx0 = max(mx0, max(c[0], c[1]));
        mx1 = max(mx1, max(c[2], c[3]));
        c[0] = c[1] = c[2] = c[3] = 0;                 // keys 16nt+8..+15
        mma_s8(c, a0, b0[2], b0[3]);
        mma_s8(c, a1, b1[2], b1[3]);
        mx0 = max(mx0, max(c[0], c[1]));
        mx1 = max(mx1, max(c[2], c[3]));
    }
    // reduce max across the 4 lanes sharing each row
    mx0 = max(mx0, __shfl_xor_sync(0xffffffffu, mx0, 1));
    mx0 = max(mx0, __shfl_xor_sync(0xffffffffu, mx0, 2));
    mx1 = max(mx1, __shfl_xor_sync(0xffffffffu, mx1, 1));
    mx1 = max(mx1, __shfl_xor_sync(0xffffffffu, mx1, 2));

    // ---- pass B: Z + argmax position ----
    float Z0 = 0.0f, Z1 = 0.0f;
    int pos0 = -1, pos1 = -1;
#pragma unroll 4
    for (int nt = 0; nt < 64; nt++) {
        const uint32_t ka = kaddr + (uint32_t)(nt * 16 * 80);
        uint32_t b0[4], b1[4];
        ldm_x4(b0[0], b0[1], b0[2], b0[3], ka);
        ldm_x4(b1[0], b1[1], b1[2], b1[3], ka + 32);
#pragma unroll
        for (int oct = 0; oct < 2; oct++) {
            int c[4];
            c[0] = c[1] = c[2] = c[3] = 0;
            if (oct == 0) {
                mma_s8(c, a0, b0[0], b0[1]);
                mma_s8(c, a1, b1[0], b1[1]);
            } else {
                mma_s8(c, a0, b0[2], b0[3]);
                mma_s8(c, a1, b1[2], b1[3]);
            }
            const int key0 = 16 * nt + 8 * oct + 2 * (lane & 3);
            Z0 += table[c[0] - mx0 + 128];
            Z0 += table[c[1] - mx0 + 128];
            Z1 += table[c[2] - mx1 + 128];
            Z1 += table[c[3] - mx1 + 128];
            if (c[0] == mx0) pos0 = key0;
            if (c[1] == mx0) pos0 = key0 + 1;
            if (c[2] == mx1) pos1 = key0;
            if (c[3] == mx1) pos1 = key0 + 1;
        }
    }
    Z0 += __shfl_xor_sync(0xffffffffu, Z0, 1);
    Z0 += __shfl_xor_sync(0xffffffffu, Z0, 2);
    Z1 += __shfl_xor_sync(0xffffffffu, Z1, 1);
    Z1 += __shfl_xor_sync(0xffffffffu, Z1, 2);
    pos0 = max(pos0, __shfl_xor_sync(0xffffffffu, pos0, 1));
    pos0 = max(pos0, __shfl_xor_sync(0xffffffffu, pos0, 2));
    pos1 = max(pos1, __shfl_xor_sync(0xffffffffu, pos1, 1));
    pos1 = max(pos1, __shfl_xor_sync(0xffffffffu, pos1, 2));

    const bool s0 = (1.0f / Z0 + 0.5f) >= 1.0f;
    const bool s1 = (1.0f / Z1 + 0.5f) >= 1.0f;

    // output: rows rowBase + wid*16 + lane/4 (+8); lane writes bytes (lane&3)*16
    const int seg = (lane & 3) * 16;
    const int rlo = rowBase + wid * 16 + (lane >> 2);
    const int rhi = rlo + 8;

    int4 o0 = make_int4(0, 0, 0, 0), o1 = make_int4(0, 0, 0, 0);
    if (s0) o0 = *(const int4*)(vbase + (size_t)pos0 * 64 + seg);
    if (s1) o1 = *(const int4*)(vbase + (size_t)pos1 * 64 + seg);
    if (s0 || s1) g_flag[bb * 8 + blockIdx.y] = 1;
    *(int4*)(g_t + (size_t)(bb * 1024 + rlo) * 768 + h * 64 + seg) = o0;
    *(int4*)(g_t + (size_t)(bb * 1024 + rhi) * 768 + h * 64 + seg) = o1;
}

// ---------------------------------------------------------------------------
// GEMM2: Out[m,o] = tern( sum_c T[m,c]*Wproj[o,c] )  (M=8192,N=768,K=768)
// Fast path: group with no attention spike -> output exactly zero.
// ---------------------------------------------------------------------------
__global__ void __launch_bounds__(256, 2) gemm_proj_kernel(const float* __restrict__ W,
                                                           float* __restrict__ Out) {
    __shared__ float As[2][16][132];
    __shared__ float Bs[2][16][132];
    const int tid = threadIdx.x;
    const int tx = tid & 15, ty = tid >> 4;
    const int rowBase = blockIdx.y * 128;
    const int colBase = blockIdx.x * 128;

    if (g_flag[blockIdx.y] == 0) {
        const float4 z = make_float4(0.f, 0.f, 0.f, 0.f);
#pragma unroll
        for (int i = 0; i < 8; i++) {
            float* op = Out + (size_t)(rowBase + ty * 8 + i) * 768 + colBase + tx * 8;
            *(float4*)op = z;
            *(float4*)(op + 4) = z;
        }
        return;
    }

    const int lr = tid >> 1;
    const int lk = (tid & 1) * 8;
    const float* Bg = W + (size_t)(colBase + lr) * 768 + lk;
    const signed char* Agc = g_t + (size_t)(rowBase + (tid & 127)) * 768;

    float acc[8][8];
#pragma unroll
    for (int i = 0; i < 8; i++)
#pragma unroll
        for (int j = 0; j < 8; j++) acc[i][j] = 0.0f;

    if (tid < 128) {
        const int4 raw = *(const int4*)(Agc);
        const signed char* cp = (const signed char*)&raw;
#pragma unroll
        for (int k2 = 0; k2 < 16; k2++) As[0][k2][tid] = (float)cp[k2];
    }
    {
        const float4 b0 = *(const float4*)Bg;
        const float4 b1 = *(const float4*)(Bg + 4);
        Bs[0][lk + 0][lr] = b0.x; Bs[0][lk + 1][lr] = b0.y;
        Bs[0][lk + 2][lr] = b0.z; Bs[0][lk + 3][lr] = b0.w;
        Bs[0][lk + 4][lr] = b1.x; Bs[0][lk + 5][lr] = b1.y;
        Bs[0][lk + 6][lr] = b1.z; Bs[0][lk + 7][lr] = b1.w;
    }
    __syncthreads();

    int buf = 0;
    for (int kt = 0; kt < 768; kt += 16) {
        int4 nraw; float4 nb0, nb1;
        const bool nxt = (kt + 16) < 768;
        if (nxt) {
            if (tid < 128) nraw = *(const int4*)(Agc + kt + 16);
            nb0 = *(const float4*)(Bg + kt + 16);
            nb1 = *(const float4*)(Bg + kt + 20);
        }
#pragma unroll
        for (int kk = 0; kk < 16; kk++) {
            float a[8], b[8];
            *(float4*)(a)     = *(const float4*)&As[buf][kk][ty * 8];
            *(float4*)(a + 4) = *(const float4*)&As[buf][kk][ty * 8 + 4];
            *(float4*)(b)     = *(const float4*)&Bs[buf][kk][tx * 8];
            *(float4*)(b + 4) = *(const float4*)&Bs[buf][kk][tx * 8 + 4];
#pragma unroll
            for (int i = 0; i < 8; i++)
#pragma unroll
                for (int j = 0; j < 8; j++) acc[i][j] = fmaf(a[i], b[j], acc[i][j]);
        }
        if (nxt) {
            const int nb2 = buf ^ 1;
            if (tid < 128) {
                const signed char* cp = (const signed char*)&nraw;
#pragma unroll
                for (int k2 = 0; k2 < 16; k2++) As[nb2][k2][tid] = (float)cp[k2];
            }
            Bs[nb2][lk + 0][lr] = nb0.x; Bs[nb2][lk + 1][lr] = nb0.y;
            Bs[nb2][lk + 2][lr] = nb0.z; Bs[nb2][lk + 3][lr] = nb0.w;
            Bs[nb2][lk + 4][lr] = nb1.x; Bs[nb2][lk + 5][lr] = nb1.y;
            Bs[nb2][lk + 6][lr] = nb1.z; Bs[nb2][lk + 7][lr] = nb1.w;
        }
        __syncthreads();
        buf ^= 1;
    }

#pragma unroll
    for (int i = 0; i < 8; i++) {
        const int row = rowBase + ty * 8 + i;
        float o[8];
#pragma unroll
        for (int j = 0; j < 8; j++) {
            const float u = acc[i][j] + 0.5f;
            o[j] = (u >= 1.0f) ? 1.0f : ((u < 0.0f) ? -1.0f : 0.0f);
        }
        float* op = Out + (size_t)row * 768 + colBase + tx * 8;
        *(float4*)op       = make_float4(o[0], o[1], o[2], o[3]);
        *(float4*)(op + 4) = make_float4(o[4], o[5], o[6], o[7]);
    }
}

// ---------------------------------------------------------------------------
extern "C" void kernel_launch(void* const* d_in, const int* in_sizes, int n_in,
                              void* d_out, int out_size) {
    (void)in_sizes; (void)n_in; (void)out_size;
    const float* x      = (const float*)d_in[0];
    const float* w_qkv  = (const float*)d_in[1];
    const float* w_proj = (const float*)d_in[2];
    float* out = (float*)d_out;

    cudaFuncSetAttribute(attn_kernel, cudaFuncAttributeMaxDynamicSharedMemorySize, ATTN_SMEM);

    split_kernel<<<7872, 256>>>(x, w_qkv);                      // 2,015,232 float4s
    gemm_qkv_kernel<<<dim3(18, 64), 256, QKV_SMEM>>>();         // N=2304/128, M=8192/128
    attn_kernel<<<dim3(96, 8), 256, ATTN_SMEM>>>();             // (b*h), 128-row groups
    gemm_proj_kernel<<<dim3(6, 64), 256>>>(w_proj, out);
}